// round 7
// baseline (speedup 1.0000x reference)
#include <cuda_runtime.h>
#include <cuda_bf16.h>

// SilkNNUE: out[r] = MLP( relu( sum_{k<29} emb[x[r,k]] ) )
// Layer2: 128->32 (+b2), CReLU -> 64
// Layer3: 64->32  (+b3), CReLU -> 64
// Layer4: 64->1
//
// R3: batch 8 rows per warp through gather + MLP so each weight LDS feeds
// 8 rows (8x less smem weight traffic — the R2 L1TEX bottleneck) and the
// gather has MLP=8 loads in flight.

#define WARPS_PER_BLOCK 8
#define ROWS_PER_WARP   8
#define ROWS_PER_BLOCK  (WARPS_PER_BLOCK * ROWS_PER_WARP)
#define FULLMASK 0xffffffffu

__global__ __launch_bounds__(256) void silk_nnue_kernel(
    const int*   __restrict__ x,     // (nrows, 32) int32, first 29 cols used
    const float* __restrict__ emb,   // (14848, 128)
    const float* __restrict__ w2,    // (32, 128)
    const float* __restrict__ b2,    // (32,)
    const float* __restrict__ w3,    // (32, 64)
    const float* __restrict__ b3,    // (32,)
    const float* __restrict__ w4,    // (1, 64)
    float*       __restrict__ out,   // (nrows,)
    int nrows)
{
    // Transposed weights: consecutive lanes read consecutive floats (no conflicts).
    __shared__ float w2t[128 * 32];   // w2t[k*32 + j] = w2[j*128 + k]
    __shared__ float w3t[64 * 32];    // w3t[k*32 + i] = w3[i*64 + k]
    __shared__ float b2s[32], b3s[32], w4s[64];
    __shared__ float hsm[WARPS_PER_BLOCK][ROWS_PER_WARP][128];

    const int tid = threadIdx.x;

    for (int i = tid; i < 32 * 128; i += 256) {
        int j = i >> 7, k = i & 127;
        w2t[k * 32 + j] = w2[i];
    }
    for (int i = tid; i < 32 * 64; i += 256) {
        int j = i >> 6, k = i & 63;
        w3t[k * 32 + j] = w3[i];
    }
    if (tid < 32) { b2s[tid] = b2[tid]; b3s[tid] = b3[tid]; }
    if (tid < 64) { w4s[tid] = w4[tid]; }
    __syncthreads();

    const int warp = tid >> 5;
    const int lane = tid & 31;
    const int row0 = blockIdx.x * ROWS_PER_BLOCK + warp * ROWS_PER_WARP;
    if (row0 >= nrows) return;
    const int rlast = nrows - 1;

    const float4* __restrict__ emb4 = (const float4*)emb;

    // ---- index prefetch: lane l holds column l's index for each of 8 rows ----
    int myidx[ROWS_PER_WARP];
    #pragma unroll
    for (int r = 0; r < ROWS_PER_WARP; r++) {
        const int rr = min(row0 + r, rlast);
        myidx[r] = x[rr * 32 + lane];
    }

    // ---- gather-sum: 8 independent LDG.128 in flight per k-step ----
    float4 acc[ROWS_PER_WARP];
    #pragma unroll
    for (int r = 0; r < ROWS_PER_WARP; r++)
        acc[r] = make_float4(0.f, 0.f, 0.f, 0.f);

    #pragma unroll 1
    for (int k = 0; k < 29; k++) {
        #pragma unroll
        for (int r = 0; r < ROWS_PER_WARP; r++) {
            const int idx = __shfl_sync(FULLMASK, myidx[r], k);
            const float4 e = emb4[(long)idx * 32 + lane];  // coalesced 512B/warp
            acc[r].x += e.x; acc[r].y += e.y;
            acc[r].z += e.z; acc[r].w += e.w;
        }
    }

    // ---- ReLU + stage h for all 8 rows ----
    #pragma unroll
    for (int r = 0; r < ROWS_PER_WARP; r++) {
        float4 hv;
        hv.x = fmaxf(acc[r].x, 0.f);
        hv.y = fmaxf(acc[r].y, 0.f);
        hv.z = fmaxf(acc[r].z, 0.f);
        hv.w = fmaxf(acc[r].w, 0.f);
        ((float4*)hsm[warp][r])[lane] = hv;   // conflict-free STS.128
    }
    __syncwarp();

    // ---- layer 2: each weight LDS amortized over 8 rows ----
    float s[ROWS_PER_WARP];
    #pragma unroll
    for (int r = 0; r < ROWS_PER_WARP; r++) s[r] = 0.f;

    const float* __restrict__ w2p = w2t + lane;
    #pragma unroll 4
    for (int k = 0; k < 128; k += 4) {
        const float wa = w2p[(k + 0) * 32];
        const float wb = w2p[(k + 1) * 32];
        const float wc = w2p[(k + 2) * 32];
        const float wd = w2p[(k + 3) * 32];
        #pragma unroll
        for (int r = 0; r < ROWS_PER_WARP; r++) {
            const float4 hh = *(const float4*)(&hsm[warp][r][k]);  // broadcast
            s[r] += hh.x * wa + hh.y * wb + hh.z * wc + hh.w * wd;
        }
    }
    float o2[ROWS_PER_WARP];
    #pragma unroll
    for (int r = 0; r < ROWS_PER_WARP; r++)
        o2[r] = b2s[lane] + s[r];

    // ---- layer 3 (fused CReLU), weights amortized over 8 rows ----
    float t0[ROWS_PER_WARP], t1[ROWS_PER_WARP];
    #pragma unroll
    for (int r = 0; r < ROWS_PER_WARP; r++) { t0[r] = 0.f; t1[r] = 0.f; }

    const float* __restrict__ w3p = w3t + lane;
    #pragma unroll 4
    for (int j = 0; j < 32; j++) {
        const float wa = w3p[j * 32];
        const float wb = w3p[(32 + j) * 32];
        #pragma unroll
        for (int r = 0; r < ROWS_PER_WARP; r++) {
            const float t = __shfl_sync(FULLMASK, o2[r], j);
            t0[r] += fmaxf(t, 0.f)  * wa;
            t1[r] += fmaxf(-t, 0.f) * wb;
        }
    }

    // ---- layer 4 (fused CReLU) + warp reduction per row ----
    #pragma unroll
    for (int r = 0; r < ROWS_PER_WARP; r++) {
        const float o3 = b3s[lane] + t0[r] + t1[r];
        float g = fmaxf(o3, 0.f) * w4s[lane] + fmaxf(-o3, 0.f) * w4s[32 + lane];
        #pragma unroll
        for (int off = 16; off; off >>= 1)
            g += __shfl_xor_sync(FULLMASK, g, off);
        if (lane == 0 && (row0 + r) < nrows) out[row0 + r] = g;
    }
}

extern "C" void kernel_launch(void* const* d_in, const int* in_sizes, int n_in,
                              void* d_out, int out_size)
{
    const int*   x   = (const int*)  d_in[0];
    const float* emb = (const float*)d_in[1];
    const float* w2  = (const float*)d_in[2];
    const float* b2  = (const float*)d_in[3];
    const float* w3  = (const float*)d_in[4];
    const float* b3  = (const float*)d_in[5];
    const float* w4  = (const float*)d_in[6];
    float* out = (float*)d_out;

    const int nrows  = in_sizes[0] / 32;
    const int blocks = (nrows + ROWS_PER_BLOCK - 1) / ROWS_PER_BLOCK;
    silk_nnue_kernel<<<blocks, 256>>>(x, emb, w2, b2, w3, b3, w4, out, nrows);
}

// round 8
// speedup vs baseline: 1.4310x; 1.4310x over previous
#include <cuda_runtime.h>
#include <cuda_bf16.h>

// SilkNNUE: out[r] = MLP( relu( sum_{k<29} emb[x[r,k]] ) )
// Layer2: 128->32 (+b2), CReLU -> 64
// Layer3: 64->32  (+b3), CReLU -> 64
// Layer4: 64->1
//
// R3: batch 8 rows per warp through gather + MLP so each weight LDS feeds
// 8 rows (8x less smem weight traffic — the R2 L1TEX bottleneck) and the
// gather has MLP=8 loads in flight.

#define WARPS_PER_BLOCK 8
#define ROWS_PER_WARP   8
#define ROWS_PER_BLOCK  (WARPS_PER_BLOCK * ROWS_PER_WARP)
#define FULLMASK 0xffffffffu

__global__ __launch_bounds__(256) void silk_nnue_kernel(
    const int*   __restrict__ x,     // (nrows, 32) int32, first 29 cols used
    const float* __restrict__ emb,   // (14848, 128)
    const float* __restrict__ w2,    // (32, 128)
    const float* __restrict__ b2,    // (32,)
    const float* __restrict__ w3,    // (32, 64)
    const float* __restrict__ b3,    // (32,)
    const float* __restrict__ w4,    // (1, 64)
    float*       __restrict__ out,   // (nrows,)
    int nrows)
{
    // Transposed weights: consecutive lanes read consecutive floats (no conflicts).
    __shared__ float w2t[128 * 32];   // w2t[k*32 + j] = w2[j*128 + k]
    __shared__ float w3t[64 * 32];    // w3t[k*32 + i] = w3[i*64 + k]
    __shared__ float b2s[32], b3s[32], w4s[64];
    __shared__ float hsm[WARPS_PER_BLOCK][ROWS_PER_WARP][128];

    const int tid = threadIdx.x;

    for (int i = tid; i < 32 * 128; i += 256) {
        int j = i >> 7, k = i & 127;
        w2t[k * 32 + j] = w2[i];
    }
    for (int i = tid; i < 32 * 64; i += 256) {
        int j = i >> 6, k = i & 63;
        w3t[k * 32 + j] = w3[i];
    }
    if (tid < 32) { b2s[tid] = b2[tid]; b3s[tid] = b3[tid]; }
    if (tid < 64) { w4s[tid] = w4[tid]; }
    __syncthreads();

    const int warp = tid >> 5;
    const int lane = tid & 31;
    const int row0 = blockIdx.x * ROWS_PER_BLOCK + warp * ROWS_PER_WARP;
    if (row0 >= nrows) return;
    const int rlast = nrows - 1;

    const float4* __restrict__ emb4 = (const float4*)emb;

    // ---- index prefetch: lane l holds column l's index for each of 8 rows ----
    int myidx[ROWS_PER_WARP];
    #pragma unroll
    for (int r = 0; r < ROWS_PER_WARP; r++) {
        const int rr = min(row0 + r, rlast);
        myidx[r] = x[rr * 32 + lane];
    }

    // ---- gather-sum: 8 independent LDG.128 in flight per k-step ----
    float4 acc[ROWS_PER_WARP];
    #pragma unroll
    for (int r = 0; r < ROWS_PER_WARP; r++)
        acc[r] = make_float4(0.f, 0.f, 0.f, 0.f);

    #pragma unroll 1
    for (int k = 0; k < 29; k++) {
        #pragma unroll
        for (int r = 0; r < ROWS_PER_WARP; r++) {
            const int idx = __shfl_sync(FULLMASK, myidx[r], k);
            const float4 e = emb4[(long)idx * 32 + lane];  // coalesced 512B/warp
            acc[r].x += e.x; acc[r].y += e.y;
            acc[r].z += e.z; acc[r].w += e.w;
        }
    }

    // ---- ReLU + stage h for all 8 rows ----
    #pragma unroll
    for (int r = 0; r < ROWS_PER_WARP; r++) {
        float4 hv;
        hv.x = fmaxf(acc[r].x, 0.f);
        hv.y = fmaxf(acc[r].y, 0.f);
        hv.z = fmaxf(acc[r].z, 0.f);
        hv.w = fmaxf(acc[r].w, 0.f);
        ((float4*)hsm[warp][r])[lane] = hv;   // conflict-free STS.128
    }
    __syncwarp();

    // ---- layer 2: each weight LDS amortized over 8 rows ----
    float s[ROWS_PER_WARP];
    #pragma unroll
    for (int r = 0; r < ROWS_PER_WARP; r++) s[r] = 0.f;

    const float* __restrict__ w2p = w2t + lane;
    #pragma unroll 4
    for (int k = 0; k < 128; k += 4) {
        const float wa = w2p[(k + 0) * 32];
        const float wb = w2p[(k + 1) * 32];
        const float wc = w2p[(k + 2) * 32];
        const float wd = w2p[(k + 3) * 32];
        #pragma unroll
        for (int r = 0; r < ROWS_PER_WARP; r++) {
            const float4 hh = *(const float4*)(&hsm[warp][r][k]);  // broadcast
            s[r] += hh.x * wa + hh.y * wb + hh.z * wc + hh.w * wd;
        }
    }
    float o2[ROWS_PER_WARP];
    #pragma unroll
    for (int r = 0; r < ROWS_PER_WARP; r++)
        o2[r] = b2s[lane] + s[r];

    // ---- layer 3 (fused CReLU), weights amortized over 8 rows ----
    float t0[ROWS_PER_WARP], t1[ROWS_PER_WARP];
    #pragma unroll
    for (int r = 0; r < ROWS_PER_WARP; r++) { t0[r] = 0.f; t1[r] = 0.f; }

    const float* __restrict__ w3p = w3t + lane;
    #pragma unroll 4
    for (int j = 0; j < 32; j++) {
        const float wa = w3p[j * 32];
        const float wb = w3p[(32 + j) * 32];
        #pragma unroll
        for (int r = 0; r < ROWS_PER_WARP; r++) {
            const float t = __shfl_sync(FULLMASK, o2[r], j);
            t0[r] += fmaxf(t, 0.f)  * wa;
            t1[r] += fmaxf(-t, 0.f) * wb;
        }
    }

    // ---- layer 4 (fused CReLU) + warp reduction per row ----
    #pragma unroll
    for (int r = 0; r < ROWS_PER_WARP; r++) {
        const float o3 = b3s[lane] + t0[r] + t1[r];
        float g = fmaxf(o3, 0.f) * w4s[lane] + fmaxf(-o3, 0.f) * w4s[32 + lane];
        #pragma unroll
        for (int off = 16; off; off >>= 1)
            g += __shfl_xor_sync(FULLMASK, g, off);
        if (lane == 0 && (row0 + r) < nrows) out[row0 + r] = g;
    }
}

extern "C" void kernel_launch(void* const* d_in, const int* in_sizes, int n_in,
                              void* d_out, int out_size)
{
    const int*   x   = (const int*)  d_in[0];
    const float* emb = (const float*)d_in[1];
    const float* w2  = (const float*)d_in[2];
    const float* b2  = (const float*)d_in[3];
    const float* w3  = (const float*)d_in[4];
    const float* b3  = (const float*)d_in[5];
    const float* w4  = (const float*)d_in[6];
    float* out = (float*)d_out;

    const int nrows  = in_sizes[0] / 32;
    const int blocks = (nrows + ROWS_PER_BLOCK - 1) / ROWS_PER_BLOCK;
    silk_nnue_kernel<<<blocks, 256>>>(x, emb, w2, b2, w3, b3, w4, out, nrows);
}